// round 7
// baseline (speedup 1.0000x reference)
#include <cuda_runtime.h>
#include <cstdint>

// WindowEmbedding forward: out[b, t, k*D + d] = (t-k >= 0) ? in[b, t-k, d] : 0
// B=16, T=2048, D=256, W=7.
// R6: TMA bulk-store path. Stage 22 input rows in SMEM in REVERSED t order;
// then every output row (7168 B) is 7 contiguous SMEM rows -> one
// cp.async.bulk per output row. Bypasses the per-SM STG wavefront path
// entirely (the suspected ~40us wall: nothing was >72% in ncu).

#define B_DIM 16
#define T_DIM 2048
#define D_DIM 256
#define W_DIM 7

#define D4 64                         // float4 per input row
#define ROW_BYTES 1024                // one input row
#define SLICE_BYTES (W_DIM * ROW_BYTES)  // 7168 per output row
#define TILE_T 16                     // t-values per block
#define HALO (W_DIM - 1)              // 6
#define ROWS (TILE_T + HALO)          // 22 staged rows
#define NTHREADS 256

__global__ __launch_bounds__(NTHREADS) void window_embed_tma_kernel(
    const float4* __restrict__ in,   // [B, T, 64] float4
    float4* __restrict__ out)        // [B, T, 448] float4
{
    __shared__ __align__(16) float4 s[ROWS * D4];   // 22.5 KB

    const int bt0 = blockIdx.x * TILE_T;     // b*T + t0, t0 multiple of 16
    const int t0  = bt0 & (T_DIM - 1);
    const int tid = threadIdx.x;

    // Stage reversed: smem row r holds x[bt0 + 15 - r], r = 0..21.
    // Valid iff t0 + 15 - r >= 0 (only blocks with t0 == 0 have invalid rows).
    const float4 zero = make_float4(0.f, 0.f, 0.f, 0.f);
    #pragma unroll
    for (int i = tid; i < ROWS * D4; i += NTHREADS) {
        const int r  = i >> 6;
        const int ts = t0 + (TILE_T - 1) - r;
        s[i] = (ts >= 0)
             ? in[(long long)(bt0 + (TILE_T - 1) - r) * D4 + (i & 63)]
             : zero;
    }
    __syncthreads();
    // Order generic-proxy SMEM writes before async-proxy (TMA) reads.
    asm volatile("fence.proxy.async.shared::cta;" ::: "memory");

    if (tid == 0) {
        uint32_t sbase;
        asm("{ .reg .u64 t; cvta.to.shared.u64 t, %1; cvt.u32.u64 %0, t; }"
            : "=r"(sbase) : "l"((const void*)s));
        const uint64_t dst0 = (uint64_t)out + (uint64_t)bt0 * SLICE_BYTES;

        // Output row t0+j = smem rows [15-j .. 21-j] (7 contiguous KB-rows).
        #pragma unroll
        for (int j = 0; j < TILE_T; j++) {
            const uint32_t src = sbase + (uint32_t)((TILE_T - 1 - j) * ROW_BYTES);
            const uint64_t dst = dst0 + (uint64_t)j * SLICE_BYTES;
            asm volatile(
                "cp.async.bulk.global.shared::cta.bulk_group [%0], [%1], %2;"
                :: "l"(dst), "r"(src), "n"(SLICE_BYTES) : "memory");
        }
        asm volatile("cp.async.bulk.commit_group;" ::: "memory");
        asm volatile("cp.async.bulk.wait_group 0;" ::: "memory");
    }
}

extern "C" void kernel_launch(void* const* d_in, const int* in_sizes, int n_in,
                              void* d_out, int out_size)
{
    const float4* in = (const float4*)d_in[0];
    float4* out = (float4*)d_out;

    dim3 grid(B_DIM * T_DIM / TILE_T);   // 2048
    dim3 block(NTHREADS);                // 256
    window_embed_tma_kernel<<<grid, block>>>(in, out);
}